// round 16
// baseline (speedup 1.0000x reference)
#include <cuda_runtime.h>
#include <cuda_bf16.h>
#include <cstdint>

// Problem constants
static constexpr int B = 8, S = 2048, D = 1024, H = 64;
static constexpr int M = B * S;          // 16384 rows
#define NEG_INF (-1e30f)

// Scratch (bf16 hi/lo pairs; q pre-scaled by 1/8)
__device__ __nv_bfloat16 g_q_hi[M * H], g_q_lo[M * H];
__device__ __nv_bfloat16 g_k_hi[M * H], g_k_lo[M * H];
__device__ __nv_bfloat16 g_vt_hi[H * M], g_vt_lo[H * M];   // V^T [h][m]
// Transposed bf16 hi/lo weights: [3][H][D]
__device__ __nv_bfloat16 g_wt_hi[3 * H * D];
__device__ __nv_bfloat16 g_wt_lo[3 * H * D];

// ---------------------------------------------------------------------------
// Warp-MMA + async-copy helpers (compute_103-safe: sm_80 feature set)
// ---------------------------------------------------------------------------
__device__ __forceinline__ uint32_t smem_u32(const void* p) {
    uint32_t a;
    asm("{ .reg .u64 t; cvta.to.shared.u64 t, %1; cvt.u32.u64 %0, t; }"
        : "=r"(a) : "l"(p));
    return a;
}

__device__ __forceinline__ void ldsm_x4(uint32_t* r, uint32_t addr) {
    asm volatile("ldmatrix.sync.aligned.m8n8.x4.shared.b16 {%0,%1,%2,%3}, [%4];"
                 : "=r"(r[0]), "=r"(r[1]), "=r"(r[2]), "=r"(r[3])
                 : "r"(addr));
}

__device__ __forceinline__ void mma_bf16(float* c, const uint32_t* a,
                                         uint32_t b0, uint32_t b1) {
    asm volatile(
        "mma.sync.aligned.m16n8k16.row.col.f32.bf16.bf16.f32 "
        "{%0,%1,%2,%3}, {%4,%5,%6,%7}, {%8,%9}, {%0,%1,%2,%3};"
        : "+f"(c[0]), "+f"(c[1]), "+f"(c[2]), "+f"(c[3])
        : "r"(a[0]), "r"(a[1]), "r"(a[2]), "r"(a[3]), "r"(b0), "r"(b1));
}

__device__ __forceinline__ void cp_async16(uint32_t saddr, const void* gptr) {
    asm volatile("cp.async.ca.shared.global [%0], [%1], 16;"
                 :: "r"(saddr), "l"(gptr));
}
#define CP_COMMIT() asm volatile("cp.async.commit_group;" ::: "memory")
#define CP_WAIT(n)  asm volatile("cp.async.wait_group " #n ";" ::: "memory")

__device__ __forceinline__ uint32_t pack2(__nv_bfloat16 a, __nv_bfloat16 b) {
    __nv_bfloat162 t; t.x = a; t.y = b;
    return *reinterpret_cast<uint32_t*>(&t);
}

// ---------------------------------------------------------------------------
// Kernel 0: transpose+split weights -> g_wt_hi/lo [w][h][d] bf16
// ---------------------------------------------------------------------------
__global__ void prep_w_kernel(const float* __restrict__ Wq,
                              const float* __restrict__ Wk,
                              const float* __restrict__ Wv)
{
    int idx = blockIdx.x * 256 + threadIdx.x;
    if (idx >= 3 * D * H) return;
    int w = idx / (D * H);
    int r = idx % (D * H);
    int d = r / H, h = r % H;
    const float* W = (w == 0) ? Wq : (w == 1) ? Wk : Wv;
    float v = W[(size_t)d * H + h];
    __nv_bfloat16 hi = __float2bfloat16_rn(v);
    float lo = v - __bfloat162float(hi);
    size_t o = ((size_t)w * H + h) * D + d;
    g_wt_hi[o] = hi;
    g_wt_lo[o] = __float2bfloat16_rn(lo);
}

// ---------------------------------------------------------------------------
// Kernel 1: FUSED QKV projection via mma.sync bf16 (hi/lo: hh + hl + lh).
// grid = M/128, block = 256 (8 warps, 4M x 2N).  x staged + converted ONCE
// per k-chunk; all three weight B-tiles arrive via cp.async.  Epilogue
// writes q/k as bf16 hi/lo and V directly transposed (V^T hi/lo).
// ---------------------------------------------------------------------------
static constexpr int PSTR = 72;                       // padded row stride (bf16)
static constexpr int PSTR2 = PSTR * 2;                // 144 bytes
static constexpr int SM_AHI = 0;                      // [128][72] bf16
static constexpr int SM_ALO = SM_AHI + 128 * PSTR2;   // 18432
static constexpr int SM_B0  = SM_ALO + 128 * PSTR2;   // 36864; per w: hi 9216 + lo 9216
static constexpr int PROJ_SMEM = SM_B0 + 3 * 2 * 64 * PSTR2;  // 92160 B

__global__ __launch_bounds__(256) void proj_mma_kernel(
    const float* __restrict__ x,
    const float* __restrict__ bq, const float* __restrict__ bk,
    const float* __restrict__ bv)
{
    extern __shared__ char sm[];
    const uint32_t sb = smem_u32(sm);

    const int tid = threadIdx.x;
    const int wid = tid >> 5, lane = tid & 31;
    const int wm = wid >> 1;          // 0..3 (M)
    const int wn = wid & 1;           // 0..1 (N)
    const int m0 = blockIdx.x * 128;

    const int lrow = lane & 15;
    const int lkb  = (lane >> 4) * 16;

    float acc[3][2][4][4] = {};       // [wsel][mTile][nTile][c]

    for (int c = 0; c < D / 64; c++) {
        const int k0 = c * 64;
        __syncthreads();              // previous chunk's ldsm reads complete

        // ---- cp.async: 3x (hi+lo) weight tiles [64][64] bf16 ----
        #pragma unroll
        for (int w = 0; w < 3; w++) {
            const __nv_bfloat16* WH = g_wt_hi + (size_t)w * H * D;
            const __nv_bfloat16* WL = g_wt_lo + (size_t)w * H * D;
            const uint32_t bh = sb + SM_B0 + w * 2 * 64 * PSTR2;
            #pragma unroll
            for (int i = 0; i < 2; i++) {
                int idx = tid + i * 256;          // 512 uint4 slots
                int r = idx >> 3, c8 = idx & 7;
                uint32_t so = bh + r * PSTR2 + c8 * 16;
                cp_async16(so,                   WH + (size_t)r * D + k0 + c8 * 8);
                cp_async16(so + 64 * PSTR2,      WL + (size_t)r * D + k0 + c8 * 8);
            }
        }
        CP_COMMIT();

        // ---- A tile: x fp32 -> hi/lo bf16 (overlaps the cp.async) ----
        #pragma unroll
        for (int i = 0; i < 8; i++) {
            int idx = tid + i * 256;
            int r = idx >> 4, c4 = idx & 15;
            float4 v = *(const float4*)(x + (size_t)(m0 + r) * D + k0 + c4 * 4);
            __nv_bfloat16 h0 = __float2bfloat16_rn(v.x);
            __nv_bfloat16 h1 = __float2bfloat16_rn(v.y);
            __nv_bfloat16 h2 = __float2bfloat16_rn(v.z);
            __nv_bfloat16 h3 = __float2bfloat16_rn(v.w);
            uint32_t off = (uint32_t)(r * PSTR + c4 * 4) * 2;
            *(uint2*)(sm + SM_AHI + off) = make_uint2(pack2(h0, h1), pack2(h2, h3));
            __nv_bfloat16 l0 = __float2bfloat16_rn(v.x - __bfloat162float(h0));
            __nv_bfloat16 l1 = __float2bfloat16_rn(v.y - __bfloat162float(h1));
            __nv_bfloat16 l2 = __float2bfloat16_rn(v.z - __bfloat162float(h2));
            __nv_bfloat16 l3 = __float2bfloat16_rn(v.w - __bfloat162float(h3));
            *(uint2*)(sm + SM_ALO + off) = make_uint2(pack2(l0, l1), pack2(l2, l3));
        }
        CP_WAIT(0);
        __syncthreads();

        // ---- MMA over 4 k16-steps; A-frags reused across all 3 wsel ----
        #pragma unroll
        for (int ks = 0; ks < 4; ks++) {
            const uint32_t kb = ks * 32 + lkb;
            uint32_t ah[2][4], al[2][4];
            #pragma unroll
            for (int mt = 0; mt < 2; mt++) {
                uint32_t ra = (uint32_t)((wm * 32 + mt * 16 + lrow) * PSTR2) + kb;
                ldsm_x4(ah[mt], sb + SM_AHI + ra);
                ldsm_x4(al[mt], sb + SM_ALO + ra);
            }
            #pragma unroll
            for (int w = 0; w < 3; w++) {
                const uint32_t bbase = sb + SM_B0 + w * 2 * 64 * PSTR2;
                uint32_t bh[8], bl[8];
                #pragma unroll
                for (int half = 0; half < 2; half++) {
                    uint32_t rb = (uint32_t)((wn * 32 + half * 16 + lrow) * PSTR2) + kb;
                    ldsm_x4(bh + half * 4, bbase + rb);
                    ldsm_x4(bl + half * 4, bbase + 64 * PSTR2 + rb);
                }
                #pragma unroll
                for (int mt = 0; mt < 2; mt++) {
                    #pragma unroll
                    for (int nt = 0; nt < 4; nt++) {
                        const int p = (nt >> 1) * 4 + (nt & 1);
                        mma_bf16(acc[w][mt][nt], ah[mt], bh[p], bh[p + 2]);  // hh
                        mma_bf16(acc[w][mt][nt], ah[mt], bl[p], bl[p + 2]);  // hl
                        mma_bf16(acc[w][mt][nt], al[mt], bh[p], bh[p + 2]);  // lh
                    }
                }
            }
        }
    }

    // ---- epilogue ----
    const int g = lane >> 2, tg = lane & 3;
    // q (w=0, scaled) and k (w=1): bf16 hi/lo, row-major [m][h]
    #pragma unroll
    for (int w = 0; w < 2; w++) {
        __nv_bfloat16* oh = w ? g_k_hi : g_q_hi;
        __nv_bfloat16* ol = w ? g_k_lo : g_q_lo;
        const float* bi = w ? bk : bq;
        const float sc = w ? 1.0f : 0.125f;
        #pragma unroll
        for (int mt = 0; mt < 2; mt++) {
            #pragma unroll
            for (int nt = 0; nt < 4; nt++) {
                int r = m0 + wm * 32 + mt * 16 + g;
                int col = wn * 32 + nt * 8 + tg * 2;
                float b0 = bi[col], b1 = bi[col + 1];
                float p0 = (acc[w][mt][nt][0] + b0) * sc;
                float p1 = (acc[w][mt][nt][1] + b1) * sc;
                float p2 = (acc[w][mt][nt][2] + b0) * sc;
                float p3 = (acc[w][mt][nt][3] + b1) * sc;
                __nv_bfloat16 h0 = __float2bfloat16_rn(p0);
                __nv_bfloat16 h1 = __float2bfloat16_rn(p1);
                __nv_bfloat16 h2 = __float2bfloat16_rn(p2);
                __nv_bfloat16 h3 = __float2bfloat16_rn(p3);
                *(uint32_t*)(oh + (size_t)r * H + col) = pack2(h0, h1);
                *(uint32_t*)(ol + (size_t)r * H + col) =
                    pack2(__float2bfloat16_rn(p0 - __bfloat162float(h0)),
                          __float2bfloat16_rn(p1 - __bfloat162float(h1)));
                *(uint32_t*)(oh + (size_t)(r + 8) * H + col) = pack2(h2, h3);
                *(uint32_t*)(ol + (size_t)(r + 8) * H + col) =
                    pack2(__float2bfloat16_rn(p2 - __bfloat162float(h2)),
                          __float2bfloat16_rn(p3 - __bfloat162float(h3)));
            }
        }
    }
    // v (w=2): written TRANSPOSED as V^T hi/lo [h][m]
    #pragma unroll
    for (int mt = 0; mt < 2; mt++) {
        #pragma unroll
        for (int nt = 0; nt < 4; nt++) {
            int r = m0 + wm * 32 + mt * 16 + g;      // m
            int col = wn * 32 + nt * 8 + tg * 2;     // h
            float b0 = bv[col], b1 = bv[col + 1];
            float vv[4] = { acc[2][mt][nt][0] + b0, acc[2][mt][nt][1] + b1,
                            acc[2][mt][nt][2] + b0, acc[2][mt][nt][3] + b1 };
            const int rr[4]  = { r, r, r + 8, r + 8 };
            const int cc[4]  = { col, col + 1, col, col + 1 };
            #pragma unroll
            for (int e = 0; e < 4; e++) {
                __nv_bfloat16 hi = __float2bfloat16_rn(vv[e]);
                g_vt_hi[(size_t)cc[e] * M + rr[e]] = hi;
                g_vt_lo[(size_t)cc[e] * M + rr[e]] =
                    __float2bfloat16_rn(vv[e] - __bfloat162float(hi));
            }
        }
    }
}

// ---------------------------------------------------------------------------
// Kernel 2: causal flash attention, mma.sync bf16 (hi/lo, 3 terms/GEMM),
// cp.async double-buffered KV.  grid = (32, B), block = 128 (4 warps).
// qt = 31 - bx (longest CTAs first); 2 CTAs/SM (92KB smem) -> 8 warps/SM.
// ---------------------------------------------------------------------------
static constexpr int AT_QH  = 0;                      // [64][72] hi
static constexpr int AT_QL  = AT_QH + 64 * PSTR2;     // lo
static constexpr int AT_BUF = AT_QL + 64 * PSTR2;     // 2 KV buffers
static constexpr int KVBUF  = 4 * 64 * PSTR2;         // KH,KL,VH,VL = 36864
static constexpr int ATTN_SMEM = AT_BUF + 2 * KVBUF;  // 92160 B

__global__ __launch_bounds__(128) void attn_mma_kernel(float* __restrict__ out)
{
    extern __shared__ char sm[];
    const uint32_t sb = smem_u32(sm);

    const int tid = threadIdx.x;
    const int w = tid >> 5, lane = tid & 31;
    const int g = lane >> 2, tg = lane & 3;
    const int lrow = lane & 15;
    const int lkb  = (lane >> 4) * 16;
    const int bz = blockIdx.y;
    const int qt = 31 - (int)blockIdx.x;

    // ---- stage Q tile (64 rows, hi/lo) ----
    const __nv_bfloat16* qh = g_q_hi + ((size_t)bz * S + qt * 64) * H;
    const __nv_bfloat16* ql = g_q_lo + ((size_t)bz * S + qt * 64) * H;
    #pragma unroll
    for (int i = 0; i < 4; i++) {
        int idx = tid + i * 128;
        int r = idx >> 3, c8 = idx & 7;
        *(uint4*)(sm + AT_QH + r * PSTR2 + c8 * 16) =
            *(const uint4*)(qh + (size_t)r * H + c8 * 8);
        *(uint4*)(sm + AT_QL + r * PSTR2 + c8 * 16) =
            *(const uint4*)(ql + (size_t)r * H + c8 * 8);
    }

    // ---- KV staging via cp.async ----
    const __nv_bfloat16* kh_b = g_k_hi + (size_t)bz * S * H;
    const __nv_bfloat16* kl_b = g_k_lo + (size_t)bz * S * H;
    const size_t vbase = (size_t)bz * S;
    auto stage = [&](int kt, uint32_t bufoff) {
        const __nv_bfloat16* kh = kh_b + (size_t)kt * 64 * H;
        const __nv_bfloat16* kl = kl_b + (size_t)kt * 64 * H;
        const size_t vo = vbase + (size_t)kt * 64;
        #pragma unroll
        for (int i = 0; i < 4; i++) {
            int idx = tid + i * 128;
            int r = idx >> 3, c8 = idx & 7;
            uint32_t so = sb + bufoff + r * PSTR2 + c8 * 16;
            cp_async16(so,                  kh + (size_t)r * H + c8 * 8);
            cp_async16(so + 64 * PSTR2,     kl + (size_t)r * H + c8 * 8);
            cp_async16(so + 2 * 64 * PSTR2, g_vt_hi + (size_t)r * M + vo + c8 * 8);
            cp_async16(so + 3 * 64 * PSTR2, g_vt_lo + (size_t)r * M + vo + c8 * 8);
        }
    };

    stage(0, AT_BUF);
    CP_COMMIT();
    __syncthreads();     // Q visible

    // Q fragments held in registers across all KV iterations
    uint32_t aH[4][4], aL[4][4];
    #pragma unroll
    for (int ks = 0; ks < 4; ks++) {
        uint32_t ra = (uint32_t)((w * 16 + lrow) * PSTR2) + ks * 32 + lkb;
        ldsm_x4(aH[ks], sb + AT_QH + ra);
        ldsm_x4(aL[ks], sb + AT_QL + ra);
    }

    float m0 = NEG_INF, m1 = NEG_INF, l0 = 0.f, l1 = 0.f;
    float o[8][4] = {};

    for (int kt = 0; kt <= qt; kt++) {
        // FIX (R15 bug): cur must include the shared-memory base sb —
        // ldmatrix was reading from an un-based smem offset => garbage/NaN.
        const uint32_t cur = sb + AT_BUF + (uint32_t)(kt & 1) * KVBUF;
        if (kt < qt) {
            stage(kt + 1, AT_BUF + (uint32_t)((kt + 1) & 1) * KVBUF);
            CP_COMMIT();
            CP_WAIT(1);
        } else {
            CP_WAIT(0);
        }
        __syncthreads();   // tile kt visible everywhere

        const uint32_t cKH = cur, cKL = cur + 64 * PSTR2;
        const uint32_t cVH = cur + 2 * 64 * PSTR2, cVL = cur + 3 * 64 * PSTR2;

        // ---- S = Q @ K^T ----
        float s[8][4] = {};
        #pragma unroll
        for (int ks = 0; ks < 4; ks++) {
            const uint32_t kb = ks * 32 + lkb;
            #pragma unroll
            for (int half = 0; half < 4; half++) {
                uint32_t fh[4], fl[4];
                uint32_t rb = (uint32_t)((half * 16 + lrow) * PSTR2) + kb;
                ldsm_x4(fh, cKH + rb);
                ldsm_x4(fl, cKL + rb);
                #pragma unroll
                for (int j = 0; j < 2; j++) {
                    const int nt = half * 2 + j;
                    mma_bf16(s[nt], aH[ks], fh[j], fh[j + 2]);
                    mma_bf16(s[nt], aH[ks], fl[j], fl[j + 2]);
                    mma_bf16(s[nt], aL[ks], fh[j], fh[j + 2]);
                }
            }
        }

        // ---- causal mask (diag tile only) ----
        if (kt == qt) {
            const int rb = w * 16 + g;
            #pragma unroll
            for (int nt = 0; nt < 8; nt++) {
                int c0 = nt * 8 + tg * 2;
                if (c0 > rb)         s[nt][0] = NEG_INF;
                if (c0 + 1 > rb)     s[nt][1] = NEG_INF;
                if (c0 > rb + 8)     s[nt][2] = NEG_INF;
                if (c0 + 1 > rb + 8) s[nt][3] = NEG_INF;
            }
        }

        // ---- online softmax (rows g and g+8; quad = one row) ----
        float mx0 = NEG_INF, mx1 = NEG_INF;
        #pragma unroll
        for (int nt = 0; nt < 8; nt++) {
            mx0 = fmaxf(mx0, fmaxf(s[nt][0], s[nt][1]));
            mx1 = fmaxf(mx1, fmaxf(s[nt][2], s[nt][3]));
        }
        mx0 = fmaxf(mx0, __shfl_xor_sync(0xffffffffu, mx0, 1));
        mx0 = fmaxf(mx0, __shfl_xor_sync(0xffffffffu, mx0, 2));
        mx1 = fmaxf(mx1, __shfl_xor_sync(0xffffffffu, mx1, 1));
        mx1 = fmaxf(mx1, __shfl_xor_sync(0xffffffffu, mx1, 2));
        float mn0 = fmaxf(m0, mx0), mn1 = fmaxf(m1, mx1);
        float a0 = __expf(m0 - mn0), a1 = __expf(m1 - mn1);
        float rs0 = 0.f, rs1 = 0.f;
        #pragma unroll
        for (int nt = 0; nt < 8; nt++) {
            s[nt][0] = __expf(s[nt][0] - mn0);
            s[nt][1] = __expf(s[nt][1] - mn0);
            s[nt][2] = __expf(s[nt][2] - mn1);
            s[nt][3] = __expf(s[nt][3] - mn1);
            rs0 += s[nt][0] + s[nt][1];
            rs1 += s[nt][2] + s[nt][3];
        }
        rs0 += __shfl_xor_sync(0xffffffffu, rs0, 1);
        rs0 += __shfl_xor_sync(0xffffffffu, rs0, 2);
        rs1 += __shfl_xor_sync(0xffffffffu, rs1, 1);
        rs1 += __shfl_xor_sync(0xffffffffu, rs1, 2);
        l0 = l0 * a0 + rs0; m0 = mn0;
        l1 = l1 * a1 + rs1; m1 = mn1;
        #pragma unroll
        for (int ht = 0; ht < 8; ht++) {
            o[ht][0] *= a0; o[ht][1] *= a0;
            o[ht][2] *= a1; o[ht][3] *= a1;
        }

        // ---- O += P @ V  (P from registers, hi/lo) ----
        #pragma unroll
        for (int ks = 0; ks < 4; ks++) {
            uint32_t pa[4], pb[4];
            #pragma unroll
            for (int half = 0; half < 2; half++) {
                const float* sv = s[2 * ks + half];
                __nv_bfloat16 h0 = __float2bfloat16_rn(sv[0]);
                __nv_bfloat16 h1 = __float2bfloat16_rn(sv[1]);
                __nv_bfloat16 h2 = __float2bfloat16_rn(sv[2]);
                __nv_bfloat16 h3 = __float2bfloat16_rn(sv[3]);
                pa[half * 2 + 0] = pack2(h0, h1);
                pa[half * 2 + 1] = pack2(h2, h3);
                pb[half * 2 + 0] =
                    pack2(__float2bfloat16_rn(sv[0] - __bfloat162float(h0)),
                          __float2bfloat16_rn(sv[1] - __bfloat162float(h1)));
                pb[half * 2 + 1] =
                    pack2(__float2bfloat16_rn(sv[2] - __bfloat162float(h2)),
                          __float2bfloat16_rn(sv[3] - __bfloat162float(h3)));
            }
            const uint32_t kb = ks * 32 + lkb;
            #pragma unroll
            for (int half = 0; half < 4; half++) {
                uint32_t fh[4], fl[4];
                uint32_t rb = (uint32_t)((half * 16 + lrow) * PSTR2) + kb;
                ldsm_x4(fh, cVH + rb);
                ldsm_x4(fl, cVL + rb);
                #pragma unroll
                for (int j = 0; j < 2; j++) {
                    const int ht = half * 2 + j;
                    mma_bf16(o[ht], pa, fh[j], fh[j + 2]);
                    mma_bf16(o[ht], pa, fl[j], fl[j + 2]);
                    mma_bf16(o[ht], pb, fh[j], fh[j + 2]);
                }
            }
        }
        __syncthreads();   // all warps done reading buf[kt&1] before re-issue
    }

    // ---- normalize + write ----
    float inv0 = 1.0f / l0, inv1 = 1.0f / l1;
    size_t row = (size_t)bz * S + qt * 64 + w * 16 + g;
    #pragma unroll
    for (int ht = 0; ht < 8; ht++) {
        int col = ht * 8 + tg * 2;
        *(float2*)(out + row * H + col) =
            make_float2(o[ht][0] * inv0, o[ht][1] * inv0);
        *(float2*)(out + (row + 8) * H + col) =
            make_float2(o[ht][2] * inv1, o[ht][3] * inv1);
    }
}

// ---------------------------------------------------------------------------
extern "C" void kernel_launch(void* const* d_in, const int* in_sizes, int n_in,
                              void* d_out, int out_size)
{
    const float* x  = (const float*)d_in[0];
    const float* Wq = (const float*)d_in[1];
    const float* bq = (const float*)d_in[2];
    const float* Wk = (const float*)d_in[3];
    const float* bk = (const float*)d_in[4];
    const float* Wv = (const float*)d_in[5];
    const float* bv = (const float*)d_in[6];

    prep_w_kernel<<<(3 * D * H + 255) / 256, 256>>>(Wq, Wk, Wv);

    cudaFuncSetAttribute(proj_mma_kernel,
                         cudaFuncAttributeMaxDynamicSharedMemorySize, PROJ_SMEM);
    proj_mma_kernel<<<M / 128, 256, PROJ_SMEM>>>(x, bq, bk, bv);

    cudaFuncSetAttribute(attn_mma_kernel,
                         cudaFuncAttributeMaxDynamicSharedMemorySize, ATTN_SMEM);
    attn_mma_kernel<<<dim3(32, B), 128, ATTN_SMEM>>>((float*)d_out);
}

// round 17
// speedup vs baseline: 1.0379x; 1.0379x over previous
#include <cuda_runtime.h>
#include <cuda_bf16.h>
#include <cstdint>

// Problem constants
static constexpr int B = 8, S = 2048, D = 1024, H = 64;
static constexpr int M = B * S;          // 16384 rows
#define NEG_INF (-1e30f)

// Scratch (bf16 hi/lo pairs; q pre-scaled by 1/8)
__device__ __nv_bfloat16 g_q_hi[M * H], g_q_lo[M * H];
__device__ __nv_bfloat16 g_k_hi[M * H], g_k_lo[M * H];
__device__ __nv_bfloat16 g_vt_hi[H * M], g_vt_lo[H * M];   // V^T [h][m]
// Transposed bf16 hi/lo weights: [3][H][D]
__device__ __nv_bfloat16 g_wt_hi[3 * H * D];
__device__ __nv_bfloat16 g_wt_lo[3 * H * D];

// ---------------------------------------------------------------------------
// Warp-MMA + async-copy helpers (compute_103-safe: sm_80 feature set)
// ---------------------------------------------------------------------------
__device__ __forceinline__ uint32_t smem_u32(const void* p) {
    uint32_t a;
    asm("{ .reg .u64 t; cvta.to.shared.u64 t, %1; cvt.u32.u64 %0, t; }"
        : "=r"(a) : "l"(p));
    return a;
}

__device__ __forceinline__ void ldsm_x4(uint32_t* r, uint32_t addr) {
    asm volatile("ldmatrix.sync.aligned.m8n8.x4.shared.b16 {%0,%1,%2,%3}, [%4];"
                 : "=r"(r[0]), "=r"(r[1]), "=r"(r[2]), "=r"(r[3])
                 : "r"(addr));
}

__device__ __forceinline__ void mma_bf16(float* c, const uint32_t* a,
                                         uint32_t b0, uint32_t b1) {
    asm volatile(
        "mma.sync.aligned.m16n8k16.row.col.f32.bf16.bf16.f32 "
        "{%0,%1,%2,%3}, {%4,%5,%6,%7}, {%8,%9}, {%0,%1,%2,%3};"
        : "+f"(c[0]), "+f"(c[1]), "+f"(c[2]), "+f"(c[3])
        : "r"(a[0]), "r"(a[1]), "r"(a[2]), "r"(a[3]), "r"(b0), "r"(b1));
}

__device__ __forceinline__ void cp_async16(uint32_t saddr, const void* gptr) {
    asm volatile("cp.async.ca.shared.global [%0], [%1], 16;"
                 :: "r"(saddr), "l"(gptr));
}
#define CP_COMMIT() asm volatile("cp.async.commit_group;" ::: "memory")
#define CP_WAIT(n)  asm volatile("cp.async.wait_group " #n ";" ::: "memory")

__device__ __forceinline__ uint32_t pack2(__nv_bfloat16 a, __nv_bfloat16 b) {
    __nv_bfloat162 t; t.x = a; t.y = b;
    return *reinterpret_cast<uint32_t*>(&t);
}

// ---------------------------------------------------------------------------
// Kernel 0: transpose+split weights -> g_wt_hi/lo [w][h][d] bf16
// ---------------------------------------------------------------------------
__global__ void prep_w_kernel(const float* __restrict__ Wq,
                              const float* __restrict__ Wk,
                              const float* __restrict__ Wv)
{
    int idx = blockIdx.x * 256 + threadIdx.x;
    if (idx >= 3 * D * H) return;
    int w = idx / (D * H);
    int r = idx % (D * H);
    int d = r / H, h = r % H;
    const float* W = (w == 0) ? Wq : (w == 1) ? Wk : Wv;
    float v = W[(size_t)d * H + h];
    __nv_bfloat16 hi = __float2bfloat16_rn(v);
    float lo = v - __bfloat162float(hi);
    size_t o = ((size_t)w * H + h) * D + d;
    g_wt_hi[o] = hi;
    g_wt_lo[o] = __float2bfloat16_rn(lo);
}

// ---------------------------------------------------------------------------
// Kernel 1: FUSED QKV projection, 12 warps (384 thr).  Warp = (wm, wsel):
// rows wm*32..+32 of output wsel, all 64 cols.  acc = 64 floats (no spills).
// x staged+converted ONCE per chunk; weights via cp.async.  q/k written as
// bf16 hi/lo; V transposed through smem -> coalesced V^T hi/lo stores.
// ---------------------------------------------------------------------------
static constexpr int PSTR = 72;                       // padded row stride (bf16)
static constexpr int PSTR2 = PSTR * 2;                // 144 bytes
static constexpr int SM_AHI = 0;                      // [128][72] bf16
static constexpr int SM_ALO = SM_AHI + 128 * PSTR2;   // 18432
static constexpr int SM_B0  = SM_ALO + 128 * PSTR2;   // 36864; per w: hi+lo 18432
static constexpr int PROJ_SMEM = SM_B0 + 3 * 2 * 64 * PSTR2;  // 92160 B

__global__ __launch_bounds__(384) void proj_mma_kernel(
    const float* __restrict__ x,
    const float* __restrict__ bq, const float* __restrict__ bk,
    const float* __restrict__ bv)
{
    extern __shared__ char sm[];
    const uint32_t sb = smem_u32(sm);

    const int tid = threadIdx.x;
    const int wid = tid >> 5, lane = tid & 31;
    const int wm = wid & 3;           // 0..3: 32-row slice
    const int wsel = wid >> 2;        // 0..2: q/k/v
    const int m0 = blockIdx.x * 128;

    const int lrow = lane & 15;
    const int lkb  = (lane >> 4) * 16;

    float acc[2][8][4] = {};          // [mTile][n8Tile][c]  = 64 floats

    for (int c = 0; c < D / 64; c++) {
        const int k0 = c * 64;
        __syncthreads();              // previous chunk's ldsm reads complete

        // ---- cp.async: 3x (hi+lo) weight tiles [64][64] bf16 ----
        for (int i = tid; i < 1536; i += 384) {
            int w = i >> 9;                    // 0..2
            int r = (i >> 3) & 63;
            int c8 = i & 7;
            uint32_t so = sb + SM_B0 + w * (2 * 64 * PSTR2) + r * PSTR2 + c8 * 16;
            cp_async16(so,              g_wt_hi + (size_t)w * H * D + (size_t)r * D + k0 + c8 * 8);
            cp_async16(so + 64 * PSTR2, g_wt_lo + (size_t)w * H * D + (size_t)r * D + k0 + c8 * 8);
        }
        CP_COMMIT();

        // ---- A tile: x fp32 -> hi/lo bf16 (overlaps the cp.async) ----
        for (int i = tid; i < 2048; i += 384) {
            int r = i >> 4, c4 = i & 15;
            float4 v = *(const float4*)(x + (size_t)(m0 + r) * D + k0 + c4 * 4);
            __nv_bfloat16 h0 = __float2bfloat16_rn(v.x);
            __nv_bfloat16 h1 = __float2bfloat16_rn(v.y);
            __nv_bfloat16 h2 = __float2bfloat16_rn(v.z);
            __nv_bfloat16 h3 = __float2bfloat16_rn(v.w);
            uint32_t off = (uint32_t)(r * PSTR + c4 * 4) * 2;
            *(uint2*)(sm + SM_AHI + off) = make_uint2(pack2(h0, h1), pack2(h2, h3));
            __nv_bfloat16 l0 = __float2bfloat16_rn(v.x - __bfloat162float(h0));
            __nv_bfloat16 l1 = __float2bfloat16_rn(v.y - __bfloat162float(h1));
            __nv_bfloat16 l2 = __float2bfloat16_rn(v.z - __bfloat162float(h2));
            __nv_bfloat16 l3 = __float2bfloat16_rn(v.w - __bfloat162float(h3));
            *(uint2*)(sm + SM_ALO + off) = make_uint2(pack2(l0, l1), pack2(l2, l3));
        }
        CP_WAIT(0);
        __syncthreads();

        // ---- MMA over 4 k16-steps; B-frags transient (8 live regs) ----
        const uint32_t bbase = sb + SM_B0 + wsel * (2 * 64 * PSTR2);
        #pragma unroll
        for (int ks = 0; ks < 4; ks++) {
            const uint32_t kb = ks * 32 + lkb;
            uint32_t ah[2][4], al[2][4];
            #pragma unroll
            for (int mt = 0; mt < 2; mt++) {
                uint32_t ra = (uint32_t)((wm * 32 + mt * 16 + lrow) * PSTR2) + kb;
                ldsm_x4(ah[mt], sb + SM_AHI + ra);
                ldsm_x4(al[mt], sb + SM_ALO + ra);
            }
            #pragma unroll
            for (int half = 0; half < 4; half++) {
                uint32_t fh[4], fl[4];
                uint32_t rb = (uint32_t)((half * 16 + lrow) * PSTR2) + kb;
                ldsm_x4(fh, bbase + rb);
                ldsm_x4(fl, bbase + 64 * PSTR2 + rb);
                #pragma unroll
                for (int j = 0; j < 2; j++) {
                    const int nt = half * 2 + j;
                    #pragma unroll
                    for (int mt = 0; mt < 2; mt++) {
                        mma_bf16(acc[mt][nt], ah[mt], fh[j], fh[j + 2]);  // hh
                        mma_bf16(acc[mt][nt], ah[mt], fl[j], fl[j + 2]);  // hl
                        mma_bf16(acc[mt][nt], al[mt], fh[j], fh[j + 2]);  // lh
                    }
                }
            }
        }
    }
    __syncthreads();   // ALL warps done with A/B smem before vs reuse

    // ---- epilogue ----
    const int g = lane >> 2, tg = lane & 3;
    float* vs = reinterpret_cast<float*>(sm);     // reuse A region: [64][132] f32

    if (wsel < 2) {
        // q (scaled) / k: bf16 hi/lo, row-major [m][h]
        __nv_bfloat16* oh = wsel ? g_k_hi : g_q_hi;
        __nv_bfloat16* ol = wsel ? g_k_lo : g_q_lo;
        const float* bi = wsel ? bk : bq;
        const float sc = wsel ? 1.0f : 0.125f;
        #pragma unroll
        for (int mt = 0; mt < 2; mt++) {
            #pragma unroll
            for (int nt = 0; nt < 8; nt++) {
                int r = m0 + wm * 32 + mt * 16 + g;
                int col = nt * 8 + tg * 2;
                float b0 = bi[col], b1 = bi[col + 1];
                float p0 = (acc[mt][nt][0] + b0) * sc;
                float p1 = (acc[mt][nt][1] + b1) * sc;
                float p2 = (acc[mt][nt][2] + b0) * sc;
                float p3 = (acc[mt][nt][3] + b1) * sc;
                __nv_bfloat16 h0 = __float2bfloat16_rn(p0);
                __nv_bfloat16 h1 = __float2bfloat16_rn(p1);
                __nv_bfloat16 h2 = __float2bfloat16_rn(p2);
                __nv_bfloat16 h3 = __float2bfloat16_rn(p3);
                *(uint32_t*)(oh + (size_t)r * H + col) = pack2(h0, h1);
                *(uint32_t*)(ol + (size_t)r * H + col) =
                    pack2(__float2bfloat16_rn(p0 - __bfloat162float(h0)),
                          __float2bfloat16_rn(p1 - __bfloat162float(h1)));
                *(uint32_t*)(oh + (size_t)(r + 8) * H + col) = pack2(h2, h3);
                *(uint32_t*)(ol + (size_t)(r + 8) * H + col) =
                    pack2(__float2bfloat16_rn(p2 - __bfloat162float(h2)),
                          __float2bfloat16_rn(p3 - __bfloat162float(h3)));
            }
        }
    } else {
        // v: bias-add and TRANSPOSED store into smem vs[h][m_local], stride 132
        #pragma unroll
        for (int mt = 0; mt < 2; mt++) {
            #pragma unroll
            for (int nt = 0; nt < 8; nt++) {
                int rl = wm * 32 + mt * 16 + g;
                int col = nt * 8 + tg * 2;
                float b0 = bv[col], b1 = bv[col + 1];
                vs[col * 132 + rl]           = acc[mt][nt][0] + b0;
                vs[(col + 1) * 132 + rl]     = acc[mt][nt][1] + b1;
                vs[col * 132 + rl + 8]       = acc[mt][nt][2] + b0;
                vs[(col + 1) * 132 + rl + 8] = acc[mt][nt][3] + b1;
            }
        }
    }
    __syncthreads();

    // all 384 threads: vs -> g_vt hi/lo, coalesced along m
    for (int i = tid; i < 64 * 128; i += 384) {
        int h = i >> 7, mi = i & 127;
        float v = vs[h * 132 + mi];
        __nv_bfloat16 hi = __float2bfloat16_rn(v);
        g_vt_hi[(size_t)h * M + m0 + mi] = hi;
        g_vt_lo[(size_t)h * M + m0 + mi] =
            __float2bfloat16_rn(v - __bfloat162float(hi));
    }
}

// ---------------------------------------------------------------------------
// Kernel 2: causal flash attention, mma.sync bf16 (hi/lo, 3 terms/GEMM),
// cp.async double-buffered KV.  grid = (32, B), block = 128 (4 warps).
// qt = 31 - bx (longest CTAs first); 2 CTAs/SM (92KB smem).
// UNCHANGED from R16 (so the next profile prices attention exactly).
// ---------------------------------------------------------------------------
static constexpr int AT_QH  = 0;                      // [64][72] hi
static constexpr int AT_QL  = AT_QH + 64 * PSTR2;     // lo
static constexpr int AT_BUF = AT_QL + 64 * PSTR2;     // 2 KV buffers
static constexpr int KVBUF  = 4 * 64 * PSTR2;         // KH,KL,VH,VL = 36864
static constexpr int ATTN_SMEM = AT_BUF + 2 * KVBUF;  // 92160 B

__global__ __launch_bounds__(128) void attn_mma_kernel(float* __restrict__ out)
{
    extern __shared__ char sm[];
    const uint32_t sb = smem_u32(sm);

    const int tid = threadIdx.x;
    const int w = tid >> 5, lane = tid & 31;
    const int g = lane >> 2, tg = lane & 3;
    const int lrow = lane & 15;
    const int lkb  = (lane >> 4) * 16;
    const int bz = blockIdx.y;
    const int qt = 31 - (int)blockIdx.x;

    // ---- stage Q tile (64 rows, hi/lo) ----
    const __nv_bfloat16* qh = g_q_hi + ((size_t)bz * S + qt * 64) * H;
    const __nv_bfloat16* ql = g_q_lo + ((size_t)bz * S + qt * 64) * H;
    #pragma unroll
    for (int i = 0; i < 4; i++) {
        int idx = tid + i * 128;
        int r = idx >> 3, c8 = idx & 7;
        *(uint4*)(sm + AT_QH + r * PSTR2 + c8 * 16) =
            *(const uint4*)(qh + (size_t)r * H + c8 * 8);
        *(uint4*)(sm + AT_QL + r * PSTR2 + c8 * 16) =
            *(const uint4*)(ql + (size_t)r * H + c8 * 8);
    }

    // ---- KV staging via cp.async ----
    const __nv_bfloat16* kh_b = g_k_hi + (size_t)bz * S * H;
    const __nv_bfloat16* kl_b = g_k_lo + (size_t)bz * S * H;
    const size_t vbase = (size_t)bz * S;
    auto stage = [&](int kt, uint32_t bufoff) {
        const __nv_bfloat16* kh = kh_b + (size_t)kt * 64 * H;
        const __nv_bfloat16* kl = kl_b + (size_t)kt * 64 * H;
        const size_t vo = vbase + (size_t)kt * 64;
        #pragma unroll
        for (int i = 0; i < 4; i++) {
            int idx = tid + i * 128;
            int r = idx >> 3, c8 = idx & 7;
            uint32_t so = sb + bufoff + r * PSTR2 + c8 * 16;
            cp_async16(so,                  kh + (size_t)r * H + c8 * 8);
            cp_async16(so + 64 * PSTR2,     kl + (size_t)r * H + c8 * 8);
            cp_async16(so + 2 * 64 * PSTR2, g_vt_hi + (size_t)r * M + vo + c8 * 8);
            cp_async16(so + 3 * 64 * PSTR2, g_vt_lo + (size_t)r * M + vo + c8 * 8);
        }
    };

    stage(0, AT_BUF);
    CP_COMMIT();
    __syncthreads();     // Q visible

    // Q fragments held in registers across all KV iterations
    uint32_t aH[4][4], aL[4][4];
    #pragma unroll
    for (int ks = 0; ks < 4; ks++) {
        uint32_t ra = (uint32_t)((w * 16 + lrow) * PSTR2) + ks * 32 + lkb;
        ldsm_x4(aH[ks], sb + AT_QH + ra);
        ldsm_x4(aL[ks], sb + AT_QL + ra);
    }

    float m0 = NEG_INF, m1 = NEG_INF, l0 = 0.f, l1 = 0.f;
    float o[8][4] = {};

    for (int kt = 0; kt <= qt; kt++) {
        const uint32_t cur = sb + AT_BUF + (uint32_t)(kt & 1) * KVBUF;
        if (kt < qt) {
            stage(kt + 1, AT_BUF + (uint32_t)((kt + 1) & 1) * KVBUF);
            CP_COMMIT();
            CP_WAIT(1);
        } else {
            CP_WAIT(0);
        }
        __syncthreads();   // tile kt visible everywhere

        const uint32_t cKH = cur, cKL = cur + 64 * PSTR2;
        const uint32_t cVH = cur + 2 * 64 * PSTR2, cVL = cur + 3 * 64 * PSTR2;

        // ---- S = Q @ K^T ----
        float s[8][4] = {};
        #pragma unroll
        for (int ks = 0; ks < 4; ks++) {
            const uint32_t kb = ks * 32 + lkb;
            #pragma unroll
            for (int half = 0; half < 4; half++) {
                uint32_t fh[4], fl[4];
                uint32_t rb = (uint32_t)((half * 16 + lrow) * PSTR2) + kb;
                ldsm_x4(fh, cKH + rb);
                ldsm_x4(fl, cKL + rb);
                #pragma unroll
                for (int j = 0; j < 2; j++) {
                    const int nt = half * 2 + j;
                    mma_bf16(s[nt], aH[ks], fh[j], fh[j + 2]);
                    mma_bf16(s[nt], aH[ks], fl[j], fl[j + 2]);
                    mma_bf16(s[nt], aL[ks], fh[j], fh[j + 2]);
                }
            }
        }

        // ---- causal mask (diag tile only) ----
        if (kt == qt) {
            const int rb = w * 16 + g;
            #pragma unroll
            for (int nt = 0; nt < 8; nt++) {
                int c0 = nt * 8 + tg * 2;
                if (c0 > rb)         s[nt][0] = NEG_INF;
                if (c0 + 1 > rb)     s[nt][1] = NEG_INF;
                if (c0 > rb + 8)     s[nt][2] = NEG_INF;
                if (c0 + 1 > rb + 8) s[nt][3] = NEG_INF;
            }
        }

        // ---- online softmax (rows g and g+8; quad = one row) ----
        float mx0 = NEG_INF, mx1 = NEG_INF;
        #pragma unroll
        for (int nt = 0; nt < 8; nt++) {
            mx0 = fmaxf(mx0, fmaxf(s[nt][0], s[nt][1]));
            mx1 = fmaxf(mx1, fmaxf(s[nt][2], s[nt][3]));
        }
        mx0 = fmaxf(mx0, __shfl_xor_sync(0xffffffffu, mx0, 1));
        mx0 = fmaxf(mx0, __shfl_xor_sync(0xffffffffu, mx0, 2));
        mx1 = fmaxf(mx1, __shfl_xor_sync(0xffffffffu, mx1, 1));
        mx1 = fmaxf(mx1, __shfl_xor_sync(0xffffffffu, mx1, 2));
        float mn0 = fmaxf(m0, mx0), mn1 = fmaxf(m1, mx1);
        float a0 = __expf(m0 - mn0), a1 = __expf(m1 - mn1);
        float rs0 = 0.f, rs1 = 0.f;
        #pragma unroll
        for (int nt = 0; nt < 8; nt++) {
            s[nt][0] = __expf(s[nt][0] - mn0);
            s[nt][1] = __expf(s[nt][1] - mn0);
            s[nt][2] = __expf(s[nt][2] - mn1);
            s[nt][3] = __expf(s[nt][3] - mn1);
            rs0 += s[nt][0] + s[nt][1];
            rs1 += s[nt][2] + s[nt][3];
        }
        rs0 += __shfl_xor_sync(0xffffffffu, rs0, 1);
        rs0 += __shfl_xor_sync(0xffffffffu, rs0, 2);
        rs1 += __shfl_xor_sync(0xffffffffu, rs1, 1);
        rs1 += __shfl_xor_sync(0xffffffffu, rs1, 2);
        l0 = l0 * a0 + rs0; m0 = mn0;
        l1 = l1 * a1 + rs1; m1 = mn1;
        #pragma unroll
        for (int ht = 0; ht < 8; ht++) {
            o[ht][0] *= a0; o[ht][1] *= a0;
            o[ht][2] *= a1; o[ht][3] *= a1;
        }

        // ---- O += P @ V  (P from registers, hi/lo) ----
        #pragma unroll
        for (int ks = 0; ks < 4; ks++) {
            uint32_t pa[4], pb[4];
            #pragma unroll
            for (int half = 0; half < 2; half++) {
                const float* sv = s[2 * ks + half];
                __nv_bfloat16 h0 = __float2bfloat16_rn(sv[0]);
                __nv_bfloat16 h1 = __float2bfloat16_rn(sv[1]);
                __nv_bfloat16 h2 = __float2bfloat16_rn(sv[2]);
                __nv_bfloat16 h3 = __float2bfloat16_rn(sv[3]);
                pa[half * 2 + 0] = pack2(h0, h1);
                pa[half * 2 + 1] = pack2(h2, h3);
                pb[half * 2 + 0] =
                    pack2(__float2bfloat16_rn(sv[0] - __bfloat162float(h0)),
                          __float2bfloat16_rn(sv[1] - __bfloat162float(h1)));
                pb[half * 2 + 1] =
                    pack2(__float2bfloat16_rn(sv[2] - __bfloat162float(h2)),
                          __float2bfloat16_rn(sv[3] - __bfloat162float(h3)));
            }
            const uint32_t kb = ks * 32 + lkb;
            #pragma unroll
            for (int half = 0; half < 4; half++) {
                uint32_t fh[4], fl[4];
                uint32_t rb = (uint32_t)((half * 16 + lrow) * PSTR2) + kb;
                ldsm_x4(fh, cVH + rb);
                ldsm_x4(fl, cVL + rb);
                #pragma unroll
                for (int j = 0; j < 2; j++) {
                    const int ht = half * 2 + j;
                    mma_bf16(o[ht], pa, fh[j], fh[j + 2]);
                    mma_bf16(o[ht], pa, fl[j], fl[j + 2]);
                    mma_bf16(o[ht], pb, fh[j], fh[j + 2]);
                }
            }
        }
        __syncthreads();   // all warps done reading buf[kt&1] before re-issue
    }

    // ---- normalize + write ----
    float inv0 = 1.0f / l0, inv1 = 1.0f / l1;
    size_t row = (size_t)bz * S + qt * 64 + w * 16 + g;
    #pragma unroll
    for (int ht = 0; ht < 8; ht++) {
        int col = ht * 8 + tg * 2;
        *(float2*)(out + row * H + col) =
            make_float2(o[ht][0] * inv0, o[ht][1] * inv0);
        *(float2*)(out + (row + 8) * H + col) =
            make_float2(o[ht][2] * inv1, o[ht][3] * inv1);
    }
}

// ---------------------------------------------------------------------------
extern "C" void kernel_launch(void* const* d_in, const int* in_sizes, int n_in,
                              void* d_out, int out_size)
{
    const float* x  = (const float*)d_in[0];
    const float* Wq = (const float*)d_in[1];
    const float* bq = (const float*)d_in[2];
    const float* Wk = (const float*)d_in[3];
    const float* bk = (const float*)d_in[4];
    const float* Wv = (const float*)d_in[5];
    const float* bv = (const float*)d_in[6];

    prep_w_kernel<<<(3 * D * H + 255) / 256, 256>>>(Wq, Wk, Wv);

    cudaFuncSetAttribute(proj_mma_kernel,
                         cudaFuncAttributeMaxDynamicSharedMemorySize, PROJ_SMEM);
    proj_mma_kernel<<<M / 128, 384, PROJ_SMEM>>>(x, bq, bk, bv);

    cudaFuncSetAttribute(attn_mma_kernel,
                         cudaFuncAttributeMaxDynamicSharedMemorySize, ATTN_SMEM);
    attn_mma_kernel<<<dim3(32, B), 128, ATTN_SMEM>>>((float*)d_out);
}